// round 12
// baseline (speedup 1.0000x reference)
#include <cuda_runtime.h>
#include <cuda_bf16.h>

#define N_ROWS  8192
#define F_IN    512
#define HID     256
#define WDIM    64
#define BM      64
#define BK      32
#define NBLK    (N_ROWS / BM)     // 128 CTAs
#define THREADS 512

// ---- SMEM layout. Strides odd multiples of 16B => conflict-free ldmatrix ----
#define ASTRB   80
#define BSTRB   80
#define ESTRB   528
#define OFF_A0H    0
#define OFF_A0L    5120
#define OFF_A1H    10240
#define OFF_A1L    15360
#define OFF_BBASE  20480            // 3 buffers x 40960 (hi at +0, lo at +20480)
#define BBUF_SZ    40960
#define BLO        20480
#define OFF_ENC_HI 143360
#define OFF_ENC_LO 177152
#define OFF_RED    210944
#define SMEM_TOTAL 211008
#define WQ_SPLIT   40960            // lo offset within all-Wq layout

// ---- device scratch: weights transposed [n][k] + bf16 hi/lo split ----
__device__ __align__(16) __nv_bfloat16 g_W1t_hi[HID * F_IN];
__device__ __align__(16) __nv_bfloat16 g_W1t_lo[HID * F_IN];
__device__ __align__(16) __nv_bfloat16 g_W2t_hi[HID * HID];
__device__ __align__(16) __nv_bfloat16 g_W2t_lo[HID * HID];
__device__ __align__(16) __nv_bfloat16 g_Wqt_hi[WDIM * HID];
__device__ __align__(16) __nv_bfloat16 g_Wqt_lo[WDIM * HID];
__device__ float        g_part[NBLK];
__device__ unsigned int g_cnt = 0;

// ---- helpers ----
__device__ __forceinline__ unsigned smem_u32(const void* p) {
    unsigned a;
    asm("{ .reg .u64 t; cvta.to.shared.u64 t, %1; cvt.u32.u64 %0, t; }" : "=r"(a) : "l"(p));
    return a;
}
__device__ __forceinline__ void cp16(unsigned dst, const void* src) {
    asm volatile("cp.async.cg.shared.global [%0], [%1], 16;"
                 :: "r"(dst), "l"(__cvta_generic_to_global(src)) : "memory");
}
#define CP_COMMIT() asm volatile("cp.async.commit_group;" ::: "memory")
#define CP_WAIT0()  asm volatile("cp.async.wait_group 0;" ::: "memory")
#define CP_WAIT1()  asm volatile("cp.async.wait_group 1;" ::: "memory")

__device__ __forceinline__ void ldsm_x4(unsigned addr, unsigned r[4]) {
    asm volatile("ldmatrix.sync.aligned.m8n8.x4.shared.b16 {%0,%1,%2,%3}, [%4];"
                 : "=r"(r[0]), "=r"(r[1]), "=r"(r[2]), "=r"(r[3]) : "r"(addr));
}
__device__ __forceinline__ void mma16816(float d[4], const unsigned a[4],
                                         unsigned b0, unsigned b1) {
    asm volatile(
        "mma.sync.aligned.m16n8k16.row.col.f32.bf16.bf16.f32 "
        "{%0,%1,%2,%3}, {%4,%5,%6,%7}, {%8,%9}, {%0,%1,%2,%3};"
        : "+f"(d[0]), "+f"(d[1]), "+f"(d[2]), "+f"(d[3])
        : "r"(a[0]), "r"(a[1]), "r"(a[2]), "r"(a[3]), "r"(b0), "r"(b1));
}
__device__ __forceinline__ void split_pack2(float x, float y, unsigned& hi2, unsigned& lo2) {
    __nv_bfloat16 hx = __float2bfloat16(x);
    __nv_bfloat16 hy = __float2bfloat16(y);
    float rx = x - __bfloat162float(hx);
    float ry = y - __bfloat162float(hy);
    __nv_bfloat162 h; h.x = hx; h.y = hy;
    __nv_bfloat162 l; l.x = __float2bfloat16(rx); l.y = __float2bfloat16(ry);
    hi2 = *reinterpret_cast<unsigned*>(&h);
    lo2 = *reinterpret_cast<unsigned*>(&l);
}

// ---- prep: transpose + bf16 hi/lo split of weights ----
extern "C" __global__ void uqr_prep(const float* __restrict__ W1,
                                    const float* __restrict__ W2,
                                    const float* __restrict__ Wq)
{
    int idx = blockIdx.x * blockDim.x + threadIdx.x;
    float v; __nv_bfloat16 *ph, *pl; int o;
    if (idx < HID * F_IN) {
        int n = idx / F_IN, k = idx - n * F_IN;
        v = W1[k * HID + n]; ph = g_W1t_hi; pl = g_W1t_lo; o = idx;
    } else if (idx < HID * F_IN + HID * HID) {
        int j = idx - HID * F_IN;
        int n = j / HID, k = j - n * HID;
        v = W2[k * HID + n]; ph = g_W2t_hi; pl = g_W2t_lo; o = j;
    } else if (idx < HID * F_IN + HID * HID + WDIM * HID) {
        int j = idx - HID * F_IN - HID * HID;
        int n = j / HID, k = j - n * HID;
        v = Wq[k * WDIM + n]; ph = g_Wqt_hi; pl = g_Wqt_lo; o = j;
    } else return;
    __nv_bfloat16 h = __float2bfloat16(v);
    ph[o] = h;
    pl[o] = __float2bfloat16(v - __bfloat162float(h));
}

// ---- one BK=32 chunk of 3-term split GEMM, warp M-tile = 32 rows ----
// B stored [n][k] row-major => non-trans ldmatrix = col-major fragment for row.col
template<int NT>
__device__ __forceinline__ void gemm_chunk(
    unsigned aHi, unsigned aLo, int aStrB, int aK0,
    unsigned bHi, unsigned bLo,
    int wm, int wnoff, int lane, float acc[2 * NT][4])
{
#pragma unroll
    for (int ks = 0; ks < 2; ++ks) {
        const int kA = aK0 + ks * 16;
        const int kB = ks * 16;
        const int arow = wm * 32 + (lane & 15);
        const int acol = kA + ((lane >> 4) << 3);
        unsigned a0h[4], a1h[4], a0l[4], a1l[4];
        {
            unsigned aAddrH = aHi + (unsigned)(arow * aStrB + acol * 2);
            unsigned aAddrL = aLo + (unsigned)(arow * aStrB + acol * 2);
            ldsm_x4(aAddrH, a0h);
            ldsm_x4(aAddrH + 16 * aStrB, a1h);
            ldsm_x4(aAddrL, a0l);
            ldsm_x4(aAddrL + 16 * aStrB, a1l);
        }
#pragma unroll
        for (int p = 0; p < NT / 2; ++p) {
            const int brow = wnoff + p * 16 + (lane & 7) + ((lane & 16) ? 8 : 0);
            const int bcol = kB + ((lane & 8) ? 8 : 0);
            unsigned bh[4], bl[4];
            ldsm_x4(bHi + (unsigned)(brow * BSTRB + bcol * 2), bh);
            ldsm_x4(bLo + (unsigned)(brow * BSTRB + bcol * 2), bl);
            mma16816(acc[0 * NT + 2 * p],     a0h, bh[0], bh[1]);
            mma16816(acc[0 * NT + 2 * p + 1], a0h, bh[2], bh[3]);
            mma16816(acc[1 * NT + 2 * p],     a1h, bh[0], bh[1]);
            mma16816(acc[1 * NT + 2 * p + 1], a1h, bh[2], bh[3]);
            mma16816(acc[0 * NT + 2 * p],     a0h, bl[0], bl[1]);
            mma16816(acc[0 * NT + 2 * p + 1], a0h, bl[2], bl[3]);
            mma16816(acc[1 * NT + 2 * p],     a1h, bl[0], bl[1]);
            mma16816(acc[1 * NT + 2 * p + 1], a1h, bl[2], bl[3]);
            mma16816(acc[0 * NT + 2 * p],     a0l, bh[0], bh[1]);
            mma16816(acc[0 * NT + 2 * p + 1], a0l, bh[2], bh[3]);
            mma16816(acc[1 * NT + 2 * p],     a1l, bh[0], bh[1]);
            mma16816(acc[1 * NT + 2 * p + 1], a1l, bh[2], bh[3]);
        }
    }
}

// cp.async stage of a 256-row x 32-k weight chunk (both splits); 512 threads
__device__ __forceinline__ void stage_w_cp(unsigned dstHi, unsigned dstLo,
                                           const __nv_bfloat16* wh, const __nv_bfloat16* wl,
                                           int wstr, int kb, int tid)
{
    const int n    = tid >> 1;
    const int half = (tid & 1) * 32;
    const char* sh = (const char*)(wh + (size_t)n * wstr + kb);
    const char* sl = (const char*)(wl + (size_t)n * wstr + kb);
    cp16(dstHi + n * BSTRB + half,      sh + half);
    cp16(dstHi + n * BSTRB + half + 16, sh + half + 16);
    cp16(dstLo + n * BSTRB + half,      sl + half);
    cp16(dstLo + n * BSTRB + half + 16, sl + half + 16);
}

// stage ALL 8 Wq chunks (hi at +c*5120, lo at +WQ_SPLIT+c*5120); 4096 cp16 total
__device__ __forceinline__ void stage_wq_all(unsigned sbB, int tid)
{
#pragma unroll
    for (int it = 0; it < 8; ++it) {
        const int idx = it * THREADS + tid;
        const int c  = idx >> 9;            // chunk 0..7
        const int w  = idx & 511;
        const int sp = w >> 8;              // 0=hi 1=lo
        const int r  = (w >> 2) & 63;       // row 0..63
        const int j  = w & 3;               // 16B piece
        const __nv_bfloat16* src =
            (sp ? g_Wqt_lo : g_Wqt_hi) + (size_t)r * HID + c * BK + j * 8;
        cp16(sbB + sp * WQ_SPLIT + c * 5120 + r * BSTRB + j * 16, src);
    }
}

// X chunk: LDG into regs / split-store into A tile (64 rows x 32 k, 512 thr)
__device__ __forceinline__ float4 ldx(const float* __restrict__ X, int m0, int kb, int tid)
{
    const int row = tid >> 3, kq = (tid & 7) << 2;
    return *(const float4*)(X + (size_t)(m0 + row) * F_IN + kb + kq);
}
__device__ __forceinline__ void stx(char* smem, unsigned offH, unsigned offL, int tid, float4 v)
{
    const int row = tid >> 3, kq = (tid & 7) << 2;
    unsigned h0, l0, h1, l1;
    split_pack2(v.x, v.y, h0, l0);
    split_pack2(v.z, v.w, h1, l1);
    *(uint2*)(smem + offH + row * ASTRB + kq * 2) = make_uint2(h0, h1);
    *(uint2*)(smem + offL + row * ASTRB + kq * 2) = make_uint2(l0, l1);
}

// epilogue for GEMM1/2: bias + relu + split -> Enc (warp-private region)
template<int NT>
__device__ __forceinline__ void epi_relu(float acc[2 * NT][4], const float* __restrict__ bias,
                                         char* smem, int wm, int wnoff, int lane)
{
#pragma unroll
    for (int mi = 0; mi < 2; ++mi)
#pragma unroll
        for (int nj = 0; nj < NT; ++nj) {
            const int r = wm * 32 + mi * 16 + (lane >> 2);
            const int c = wnoff + nj * 8 + 2 * (lane & 3);
            const float bx = bias[c], by = bias[c + 1];
            float* a = acc[mi * NT + nj];
            float x0 = fmaxf(a[0] + bx, 0.f), y0 = fmaxf(a[1] + by, 0.f);
            float x1 = fmaxf(a[2] + bx, 0.f), y1 = fmaxf(a[3] + by, 0.f);
            unsigned h0, l0, h1, l1;
            split_pack2(x0, y0, h0, l0);
            split_pack2(x1, y1, h1, l1);
            *(unsigned*)(smem + OFF_ENC_HI + r * ESTRB + c * 2)       = h0;
            *(unsigned*)(smem + OFF_ENC_LO + r * ESTRB + c * 2)       = l0;
            *(unsigned*)(smem + OFF_ENC_HI + (r + 8) * ESTRB + c * 2) = h1;
            *(unsigned*)(smem + OFF_ENC_LO + (r + 8) * ESTRB + c * 2) = l1;
            a[0] = a[1] = a[2] = a[3] = 0.f;
        }
}

// ---- main fused kernel ----
extern "C" __global__ void __launch_bounds__(THREADS, 1)
uqr_main(const float* __restrict__ X,  const float* __restrict__ b1p,
         const float* __restrict__ b2p, const float* __restrict__ bqp,
         const float* __restrict__ Whp, const float* __restrict__ bhp,
         float* __restrict__ out)
{
    extern __shared__ char smem[];
    const unsigned sb = smem_u32(smem);
    const int tid  = threadIdx.x;
    const int lane = tid & 31;
    const int wid  = tid >> 5;          // 16 warps
    const int wm   = wid & 1;           // 2 warp-rows (32 rows each)
    const int wn   = wid >> 1;          // 8 warp-cols (32 cols each)
    const int m0   = blockIdx.x * BM;

    const unsigned aH[2] = { sb + OFF_A0H, sb + OFF_A1H };
    const unsigned aL[2] = { sb + OFF_A0L, sb + OFF_A1L };
    const unsigned bOff[3] = { sb + OFF_BBASE, sb + OFF_BBASE + BBUF_SZ,
                               sb + OFF_BBASE + 2 * BBUF_SZ };
    const unsigned eHi = sb + OFF_ENC_HI, eLo = sb + OFF_ENC_LO;

    float acc[8][4];
#pragma unroll
    for (int i = 0; i < 8; ++i)
        acc[i][0] = acc[i][1] = acc[i][2] = acc[i][3] = 0.f;

    // ============== GEMM1: enc1 = relu(X @ W1 + b1), 16 chunks ==============
    // depth-2 cp.async pipeline over 3 B buffers
    {
        float4 x = ldx(X, m0, 0, tid);
        stx((char*)smem, OFF_A0H, OFF_A0L, tid, x);
        stage_w_cp(bOff[0], bOff[0] + BLO, g_W1t_hi, g_W1t_lo, F_IN, 0, tid);
        CP_COMMIT();
        stage_w_cp(bOff[1], bOff[1] + BLO, g_W1t_hi, g_W1t_lo, F_IN, BK, tid);
        CP_COMMIT();
        CP_WAIT1();                          // chunk0 done, chunk1 flying
        __syncthreads();
    }
#pragma unroll 1
    for (int c = 0; c < F_IN / BK; ++c) {
        const int nb = (c + 1) & 1;
        float4 xn;
        if (c + 1 < F_IN / BK)
            xn = ldx(X, m0, (c + 1) * BK, tid);                 // LDG in flight
        if (c + 2 < F_IN / BK) {
            stage_w_cp(bOff[(c + 2) % 3], bOff[(c + 2) % 3] + BLO,
                       g_W1t_hi, g_W1t_lo, F_IN, (c + 2) * BK, tid);
            CP_COMMIT();
        }
        gemm_chunk<4>(aH[c & 1], aL[c & 1], ASTRB, 0,
                      bOff[c % 3], bOff[c % 3] + BLO, wm, wn * 32, lane, acc);
        if (c + 1 < F_IN / BK) {
            stx((char*)smem, nb ? OFF_A1H : OFF_A0H, nb ? OFF_A1L : OFF_A0L, tid, xn);
            if (c + 2 < F_IN / BK) CP_WAIT1(); else CP_WAIT0();
            __syncthreads();
        }
    }
    __syncthreads();                         // all warps done with buf reads
    stage_w_cp(bOff[0], bOff[0] + BLO, g_W2t_hi, g_W2t_lo, HID, 0, tid);
    CP_COMMIT();
    stage_w_cp(bOff[1], bOff[1] + BLO, g_W2t_hi, g_W2t_lo, HID, BK, tid);
    CP_COMMIT();
    epi_relu<4>(acc, b1p, (char*)smem, wm, wn * 32, lane);
    CP_WAIT1();
    __syncthreads();

    // ============== GEMM2: enc2 = relu(enc1 @ W2 + b2), 8 chunks =============
#pragma unroll 1
    for (int c = 0; c < HID / BK; ++c) {
        if (c + 2 < HID / BK) {
            stage_w_cp(bOff[(c + 2) % 3], bOff[(c + 2) % 3] + BLO,
                       g_W2t_hi, g_W2t_lo, HID, (c + 2) * BK, tid);
            CP_COMMIT();
        }
        gemm_chunk<4>(eHi, eLo, ESTRB, c * BK,
                      bOff[c % 3], bOff[c % 3] + BLO, wm, wn * 32, lane, acc);
        if (c + 2 < HID / BK)      { CP_WAIT1(); __syncthreads(); }
        else if (c + 1 < HID / BK) { CP_WAIT0(); __syncthreads(); }
    }
    __syncthreads();                       // all warps done reading Enc + bufs
    stage_wq_all(bOff[0], tid);            // ALL Wq chunks -> B region
    CP_COMMIT();
    epi_relu<4>(acc, b2p, (char*)smem, wm, wn * 32, lane);
    CP_WAIT0();
    __syncthreads();

    // ===== GEMM3: z3 = enc2 @ Wq + bq (N=64), K split across warp halves =====
    // warps wn<4: k 0..127 (chunks 0-3); wn>=4: k 128..255 (chunks 4-7)
    {
        const int grp   = (wn >= 4);
        const int wnG   = wn & 3;
        const int cbase = grp * 4;
#pragma unroll
        for (int c = 0; c < 4; ++c) {
            const unsigned wqh = bOff[0] + (cbase + c) * 5120;
            gemm_chunk<2>(eHi, eLo, ESTRB, (cbase + c) * BK,
                          wqh, wqh + WQ_SPLIT, wm, wnG * 16, lane, acc);
        }
        // cross-group combine: grp1 dumps partials, grp0 adds
        if (grp) {
            char* dst = (char*)smem + OFF_A0H + ((wid & 7) * 32 + lane) * 64;
#pragma unroll
            for (int i = 0; i < 4; ++i)
                *(float4*)(dst + i * 16) = make_float4(acc[i][0], acc[i][1], acc[i][2], acc[i][3]);
        }
        __syncthreads();
        if (!grp) {
            const char* src = (char*)smem + OFF_A0H + ((wid & 7) * 32 + lane) * 64;
#pragma unroll
            for (int i = 0; i < 4; ++i) {
                float4 v = *(const float4*)(src + i * 16);
                acc[i][0] += v.x; acc[i][1] += v.y; acc[i][2] += v.z; acc[i][3] += v.w;
            }
        }
    }

    // ===== epilogue 3: tanh + dot(Wh), deterministic reduction =====
    float s = 0.f;
    if (wn < 4) {
#pragma unroll
        for (int mi = 0; mi < 2; ++mi)
#pragma unroll
            for (int nj = 0; nj < 2; ++nj) {
                const int c = (wn & 3) * 16 + nj * 8 + 2 * (lane & 3);
                const float bx = bqp[c], by = bqp[c + 1];
                const float wx = Whp[c], wy = Whp[c + 1];
                float* a = acc[mi * 2 + nj];
                s += tanhf(a[0] + bx) * wx + tanhf(a[1] + by) * wy;
                s += tanhf(a[2] + bx) * wx + tanhf(a[3] + by) * wy;
            }
    }
#pragma unroll
    for (int o = 16; o; o >>= 1) s += __shfl_xor_sync(0xffffffffu, s, o);
    float* red = (float*)(smem + OFF_RED);
    if (lane == 0) red[wid] = s;
    __syncthreads();

    if (tid == 0) {
        float t = 0.f;
#pragma unroll
        for (int w = 0; w < 16; ++w) t += red[w];
        g_part[blockIdx.x] = t;
        __threadfence();
        unsigned old = atomicAdd(&g_cnt, 1);
        if (old == NBLK - 1) {            // last CTA: deterministic serial sum
            __threadfence();
            float acc2 = bhp[0];
#pragma unroll 8
            for (int i = 0; i < NBLK; ++i) acc2 += ((volatile float*)g_part)[i];
            out[0] = acc2;
            *((volatile unsigned*)&g_cnt) = 0;   // reset for next replay
        }
    }
}

extern "C" void kernel_launch(void* const* d_in, const int* in_sizes, int n_in,
                              void* d_out, int out_size)
{
    const float* X  = (const float*)d_in[0];
    const float* W1 = (const float*)d_in[1];
    const float* b1 = (const float*)d_in[2];
    const float* W2 = (const float*)d_in[3];
    const float* b2 = (const float*)d_in[4];
    const float* Wq = (const float*)d_in[5];
    const float* bq = (const float*)d_in[6];
    const float* Wh = (const float*)d_in[7];
    const float* bh = (const float*)d_in[8];
    float* out = (float*)d_out;

    const int prep_elems = HID * F_IN + HID * HID + WDIM * HID;
    uqr_prep<<<(prep_elems + 255) / 256, 256>>>(W1, W2, Wq);

    cudaFuncSetAttribute(uqr_main, cudaFuncAttributeMaxDynamicSharedMemorySize, SMEM_TOTAL);
    uqr_main<<<NBLK, THREADS, SMEM_TOTAL>>>(X, b1, b2, bq, Wh, bh, out);
}

// round 15
// speedup vs baseline: 1.4143x; 1.4143x over previous
#include <cuda_runtime.h>
#include <cuda_bf16.h>

#define N_ROWS  8192
#define F_IN    512
#define HID     256
#define WDIM    64
#define BM      64
#define NBLK    (N_ROWS / BM)     // 128 CTAs
#define THREADS 512

// ---- SMEM layout. Strides odd multiples of 16B => conflict-free ldmatrix ----
#define ASTRB1  272               // A mega-tile row stride (128 k * 2B + 16 pad)
#define ESTRB   528
#define ALO_OFF 17408             // lo plane offset within an A slot
#define OFF_A0  0                 // A slot 0 (hi+lo = 34816)
#define OFF_A1  34816             // A slot 1
#define OFF_ENC_HI 69632
#define OFF_ENC_LO 103424
#define OFF_RED    137216
#define SMEM_TOTAL 137280

// ---- device scratch: weights in MMA-fragment-major layout ----
// One uint4 per (n16-tile nt, k16-step ks, lane): exactly the 4 B-fragment regs
//   .x = W[nt*16 + l/4    ][ks*16 + 2m, +1]   (m = l%4, packed bf16x2, low=first)
//   .y = W[nt*16 + l/4    ][ks*16 + 8 + 2m, +1]
//   .z = W[nt*16 + 8 + l/4][ks*16 + 2m, +1]
//   .w = W[nt*16 + 8 + l/4][ks*16 + 8 + 2m, +1]
// index = (nt * NKS + ks) * 32 + lane
__device__ __align__(16) uint4 g_W1f_hi[16 * 32 * 32];
__device__ __align__(16) uint4 g_W1f_lo[16 * 32 * 32];
__device__ __align__(16) uint4 g_W2f_hi[16 * 16 * 32];
__device__ __align__(16) uint4 g_W2f_lo[16 * 16 * 32];
__device__ __align__(16) uint4 g_Wqf_hi[4 * 16 * 32];
__device__ __align__(16) uint4 g_Wqf_lo[4 * 16 * 32];
__device__ float        g_part[NBLK];
__device__ unsigned int g_cnt = 0;

// ---- helpers ----
__device__ __forceinline__ unsigned smem_u32(const void* p) {
    unsigned a;
    asm("{ .reg .u64 t; cvta.to.shared.u64 t, %1; cvt.u32.u64 %0, t; }" : "=r"(a) : "l"(p));
    return a;
}
__device__ __forceinline__ void ldsm_x4(unsigned addr, unsigned r[4]) {
    asm volatile("ldmatrix.sync.aligned.m8n8.x4.shared.b16 {%0,%1,%2,%3}, [%4];"
                 : "=r"(r[0]), "=r"(r[1]), "=r"(r[2]), "=r"(r[3]) : "r"(addr));
}
__device__ __forceinline__ void mma16816(float d[4], const unsigned a[4],
                                         unsigned b0, unsigned b1) {
    asm volatile(
        "mma.sync.aligned.m16n8k16.row.col.f32.bf16.bf16.f32 "
        "{%0,%1,%2,%3}, {%4,%5,%6,%7}, {%8,%9}, {%0,%1,%2,%3};"
        : "+f"(d[0]), "+f"(d[1]), "+f"(d[2]), "+f"(d[3])
        : "r"(a[0]), "r"(a[1]), "r"(a[2]), "r"(a[3]), "r"(b0), "r"(b1));
}
__device__ __forceinline__ void split_pack2(float x, float y, unsigned& hi2, unsigned& lo2) {
    __nv_bfloat16 hx = __float2bfloat16(x);
    __nv_bfloat16 hy = __float2bfloat16(y);
    float rx = x - __bfloat162float(hx);
    float ry = y - __bfloat162float(hy);
    __nv_bfloat162 h; h.x = hx; h.y = hy;
    __nv_bfloat162 l; l.x = __float2bfloat16(rx); l.y = __float2bfloat16(ry);
    hi2 = *reinterpret_cast<unsigned*>(&h);
    lo2 = *reinterpret_cast<unsigned*>(&l);
}

// ---- prep: build fragment-major hi/lo weight arrays ----
// W is the ORIGINAL [K][N] row-major matrix (W[k*N + n]).
__device__ __forceinline__ void make_frag(const float* __restrict__ W, int N,
                                          int nt, int ks, int lane,
                                          uint4& h, uint4& l)
{
    const int m = lane & 3, r = lane >> 2;
    const int n0 = nt * 16 + r, n1 = n0 + 8;
    const int k0 = ks * 16 + 2 * m, k1 = k0 + 8;
    unsigned hx, lx, hy, ly, hz, lz, hw, lw;
    split_pack2(W[(size_t)k0 * N + n0], W[(size_t)(k0 + 1) * N + n0], hx, lx);
    split_pack2(W[(size_t)k1 * N + n0], W[(size_t)(k1 + 1) * N + n0], hy, ly);
    split_pack2(W[(size_t)k0 * N + n1], W[(size_t)(k0 + 1) * N + n1], hz, lz);
    split_pack2(W[(size_t)k1 * N + n1], W[(size_t)(k1 + 1) * N + n1], hw, lw);
    h = make_uint4(hx, hy, hz, hw);
    l = make_uint4(lx, ly, lz, lw);
}

extern "C" __global__ void uqr_prep(const float* __restrict__ W1,
                                    const float* __restrict__ W2,
                                    const float* __restrict__ Wq)
{
    const int N1 = 16 * 32 * 32, N2 = 16 * 16 * 32, N3 = 4 * 16 * 32;
    int idx = blockIdx.x * blockDim.x + threadIdx.x;
    if (idx < N1) {
        int nt = idx >> 10, ks = (idx >> 5) & 31, lane = idx & 31;
        make_frag(W1, HID, nt, ks, lane, g_W1f_hi[idx], g_W1f_lo[idx]);
    } else if (idx < N1 + N2) {
        int j = idx - N1;
        int nt = j >> 9, ks = (j >> 5) & 15, lane = j & 31;
        make_frag(W2, HID, nt, ks, lane, g_W2f_hi[j], g_W2f_lo[j]);
    } else if (idx < N1 + N2 + N3) {
        int j = idx - N1 - N2;
        int nt = j >> 9, ks = (j >> 5) & 15, lane = j & 31;
        make_frag(Wq, WDIM, nt, ks, lane, g_Wqf_hi[j], g_Wqf_lo[j]);
    }
}

// ---- one k32 chunk of 3-term split GEMM; B direct from L2 fragments ----
template<int NT>
__device__ __forceinline__ void gemm_chunk_g(
    unsigned aHi, unsigned aLo, int aStrB, int aK0,
    const uint4* __restrict__ bHiG, const uint4* __restrict__ bLoG,
    int nks, int ntBase, int kk0,
    int wm, int lane, float acc[2 * NT][4])
{
    // load ALL B fragments for this chunk up front (LDG.128 from L2)
    uint4 BH[2][NT / 2], BL[2][NT / 2];
#pragma unroll
    for (int ks = 0; ks < 2; ++ks)
#pragma unroll
        for (int p = 0; p < NT / 2; ++p) {
            const int i = ((ntBase + p) * nks + kk0 + ks) * 32 + lane;
            BH[ks][p] = __ldg(bHiG + i);
            BL[ks][p] = __ldg(bLoG + i);
        }
#pragma unroll
    for (int ks = 0; ks < 2; ++ks) {
        const int kA = aK0 + ks * 16;
        const int arow = wm * 32 + (lane & 15);
        const int acol = kA + ((lane >> 4) << 3);
        unsigned a0h[4], a1h[4], a0l[4], a1l[4];
        const unsigned aH_ = aHi + (unsigned)(arow * aStrB + acol * 2);
        const unsigned aL_ = aLo + (unsigned)(arow * aStrB + acol * 2);
        ldsm_x4(aH_, a0h);
        ldsm_x4(aH_ + 16 * aStrB, a1h);
        ldsm_x4(aL_, a0l);
        ldsm_x4(aL_ + 16 * aStrB, a1l);
#pragma unroll
        for (int p = 0; p < NT / 2; ++p) {
            const uint4 bh = BH[ks][p], bl = BL[ks][p];
            mma16816(acc[2 * p],          a0h, bh.x, bh.y);
            mma16816(acc[2 * p + 1],      a0h, bh.z, bh.w);
            mma16816(acc[NT + 2 * p],     a1h, bh.x, bh.y);
            mma16816(acc[NT + 2 * p + 1], a1h, bh.z, bh.w);
            mma16816(acc[2 * p],          a0h, bl.x, bl.y);
            mma16816(acc[2 * p + 1],      a0h, bl.z, bl.w);
            mma16816(acc[NT + 2 * p],     a1h, bl.x, bl.y);
            mma16816(acc[NT + 2 * p + 1], a1h, bl.z, bl.w);
            mma16816(acc[2 * p],          a0l, bh.x, bh.y);
            mma16816(acc[2 * p + 1],      a0l, bh.z, bh.w);
            mma16816(acc[NT + 2 * p],     a1l, bh.x, bh.y);
            mma16816(acc[NT + 2 * p + 1], a1l, bh.z, bh.w);
        }
    }
}

// X mega-chunk (64 rows x 128 k): LDG into regs / split-store into A slot
__device__ __forceinline__ void ldx4(const float* __restrict__ X, int m0, int kb,
                                     int tid, float4 xr[4])
{
    const int row = tid >> 3, kq = (tid & 7) << 4;
    const float4* p = (const float4*)(X + (size_t)(m0 + row) * F_IN + kb + kq);
    xr[0] = p[0]; xr[1] = p[1]; xr[2] = p[2]; xr[3] = p[3];
}
__device__ __forceinline__ void stx4(char* smem, unsigned offH, int tid, const float4 xr[4])
{
    const int row = tid >> 3, kq = (tid & 7) << 4;
    unsigned h[8], l[8];
#pragma unroll
    for (int i = 0; i < 4; ++i) {
        split_pack2(xr[i].x, xr[i].y, h[2 * i],     l[2 * i]);
        split_pack2(xr[i].z, xr[i].w, h[2 * i + 1], l[2 * i + 1]);
    }
    uint4* dh = (uint4*)(smem + offH + row * ASTRB1 + kq * 2);
    uint4* dl = (uint4*)(smem + offH + ALO_OFF + row * ASTRB1 + kq * 2);
    dh[0] = make_uint4(h[0], h[1], h[2], h[3]);
    dh[1] = make_uint4(h[4], h[5], h[6], h[7]);
    dl[0] = make_uint4(l[0], l[1], l[2], l[3]);
    dl[1] = make_uint4(l[4], l[5], l[6], l[7]);
}

// epilogue for GEMM1/2: bias + relu + split -> Enc (warp-private region)
template<int NT>
__device__ __forceinline__ void epi_relu(float acc[2 * NT][4], const float* __restrict__ bias,
                                         char* smem, int wm, int wnoff, int lane)
{
#pragma unroll
    for (int mi = 0; mi < 2; ++mi)
#pragma unroll
        for (int nj = 0; nj < NT; ++nj) {
            const int r = wm * 32 + mi * 16 + (lane >> 2);
            const int c = wnoff + nj * 8 + 2 * (lane & 3);
            const float bx = bias[c], by = bias[c + 1];
            float* a = acc[mi * NT + nj];
            float x0 = fmaxf(a[0] + bx, 0.f), y0 = fmaxf(a[1] + by, 0.f);
            float x1 = fmaxf(a[2] + bx, 0.f), y1 = fmaxf(a[3] + by, 0.f);
            unsigned h0, l0, h1, l1;
            split_pack2(x0, y0, h0, l0);
            split_pack2(x1, y1, h1, l1);
            *(unsigned*)(smem + OFF_ENC_HI + r * ESTRB + c * 2)       = h0;
            *(unsigned*)(smem + OFF_ENC_LO + r * ESTRB + c * 2)       = l0;
            *(unsigned*)(smem + OFF_ENC_HI + (r + 8) * ESTRB + c * 2) = h1;
            *(unsigned*)(smem + OFF_ENC_LO + (r + 8) * ESTRB + c * 2) = l1;
            a[0] = a[1] = a[2] = a[3] = 0.f;
        }
}

// ---- main fused kernel ----
extern "C" __global__ void __launch_bounds__(THREADS, 1)
uqr_main(const float* __restrict__ X,  const float* __restrict__ b1p,
         const float* __restrict__ b2p, const float* __restrict__ bqp,
         const float* __restrict__ Whp, const float* __restrict__ bhp,
         float* __restrict__ out)
{
    extern __shared__ char smem[];
    const unsigned sb = smem_u32(smem);
    const int tid  = threadIdx.x;
    const int lane = tid & 31;
    const int wid  = tid >> 5;          // 16 warps
    const int wm   = wid & 1;           // 2 warp-rows (32 rows each)
    const int wn   = wid >> 1;          // 8 warp-cols (32 cols each)
    const int m0   = blockIdx.x * BM;

    const unsigned eHi = sb + OFF_ENC_HI, eLo = sb + OFF_ENC_LO;

    float acc[8][4];
#pragma unroll
    for (int i = 0; i < 8; ++i)
        acc[i][0] = acc[i][1] = acc[i][2] = acc[i][3] = 0.f;

    // ====== GEMM1: enc1 = relu(X @ W1 + b1); 4 A mega-chunks (BK=128) ======
    {
        float4 xr[4];
        ldx4(X, m0, 0, tid, xr);
        stx4((char*)smem, OFF_A0, tid, xr);
        __syncthreads();
    }
#pragma unroll 1
    for (int mc = 0; mc < 4; ++mc) {
        float4 xn[4];
        if (mc < 3) ldx4(X, m0, (mc + 1) * 128, tid, xn);     // LDG in flight
        const unsigned ah = sb + ((mc & 1) ? OFF_A1 : OFF_A0);
#pragma unroll
        for (int sub = 0; sub < 4; ++sub)
            gemm_chunk_g<4>(ah, ah + ALO_OFF, ASTRB1, sub * 32,
                            g_W1f_hi, g_W1f_lo, 32, wn * 2, mc * 8 + sub * 2,
                            wm, lane, acc);
        if (mc < 3) {
            stx4((char*)smem, (mc & 1) ? OFF_A0 : OFF_A1, tid, xn);
            __syncthreads();            // one barrier per mega-chunk
        }
    }
    epi_relu<4>(acc, b1p, (char*)smem, wm, wn * 32, lane);
    __syncthreads();

    // ====== GEMM2: enc2 = relu(enc1 @ W2 + b2); NO staging, NO barriers =====
#pragma unroll 1
    for (int kk = 0; kk < 16; kk += 2)
        gemm_chunk_g<4>(eHi, eLo, ESTRB, kk * 16,
                        g_W2f_hi, g_W2f_lo, 16, wn * 2, kk, wm, lane, acc);
    __syncthreads();                    // all warps done reading Enc
    epi_relu<4>(acc, b2p, (char*)smem, wm, wn * 32, lane);
    __syncthreads();

    // ====== GEMM3: z3 = enc2 @ Wq + bq (N=64); K split across warp halves ===
    {
        const int grp   = (wn >= 4);
        const int wnG   = wn & 3;
        const int cbase = grp * 4;
#pragma unroll
        for (int c = 0; c < 4; ++c)
            gemm_chunk_g<2>(eHi, eLo, ESTRB, (cbase + c) * 32,
                            g_Wqf_hi, g_Wqf_lo, 16, wnG, (cbase + c) * 2,
                            wm, lane, acc);
        // cross-group combine via smem scratch (A region is free)
        if (grp) {
            char* dst = (char*)smem + ((wid & 7) * 32 + lane) * 64;
#pragma unroll
            for (int i = 0; i < 4; ++i)
                *(float4*)(dst + i * 16) =
                    make_float4(acc[i][0], acc[i][1], acc[i][2], acc[i][3]);
        }
        __syncthreads();
        if (!grp) {
            const char* src = (char*)smem + ((wid & 7) * 32 + lane) * 64;
#pragma unroll
            for (int i = 0; i < 4; ++i) {
                float4 v = *(const float4*)(src + i * 16);
                acc[i][0] += v.x; acc[i][1] += v.y; acc[i][2] += v.z; acc[i][3] += v.w;
            }
        }
    }

    // ===== epilogue 3: tanh + dot(Wh), deterministic reduction =====
    float s = 0.f;
    if (wn < 4) {
#pragma unroll
        for (int mi = 0; mi < 2; ++mi)
#pragma unroll
            for (int nj = 0; nj < 2; ++nj) {
                const int c = (wn & 3) * 16 + nj * 8 + 2 * (lane & 3);
                const float bx = bqp[c], by = bqp[c + 1];
                const float wx = Whp[c], wy = Whp[c + 1];
                float* a = acc[mi * 2 + nj];
                s += tanhf(a[0] + bx) * wx + tanhf(a[1] + by) * wy;
                s += tanhf(a[2] + bx) * wx + tanhf(a[3] + by) * wy;
            }
    }
#pragma unroll
    for (int o = 16; o; o >>= 1) s += __shfl_xor_sync(0xffffffffu, s, o);
    float* red = (float*)(smem + OFF_RED);
    if (lane == 0) red[wid] = s;
    __syncthreads();

    if (tid == 0) {
        float t = 0.f;
#pragma unroll
        for (int w = 0; w < 16; ++w) t += red[w];
        g_part[blockIdx.x] = t;
        __threadfence();
        unsigned old = atomicAdd(&g_cnt, 1);
        if (old == NBLK - 1) {            // last CTA: deterministic serial sum
            __threadfence();
            float acc2 = bhp[0];
#pragma unroll 8
            for (int i = 0; i < NBLK; ++i) acc2 += ((volatile float*)g_part)[i];
            out[0] = acc2;
            *((volatile unsigned*)&g_cnt) = 0;   // reset for next replay
        }
    }
}

extern "C" void kernel_launch(void* const* d_in, const int* in_sizes, int n_in,
                              void* d_out, int out_size)
{
    const float* X  = (const float*)d_in[0];
    const float* W1 = (const float*)d_in[1];
    const float* b1 = (const float*)d_in[2];
    const float* W2 = (const float*)d_in[3];
    const float* b2 = (const float*)d_in[4];
    const float* Wq = (const float*)d_in[5];
    const float* bq = (const float*)d_in[6];
    const float* Wh = (const float*)d_in[7];
    const float* bh = (const float*)d_in[8];
    float* out = (float*)d_out;

    const int prep_elems = 16 * 32 * 32 + 16 * 16 * 32 + 4 * 16 * 32;
    uqr_prep<<<(prep_elems + 255) / 256, 256>>>(W1, W2, Wq);

    cudaFuncSetAttribute(uqr_main, cudaFuncAttributeMaxDynamicSharedMemorySize, SMEM_TOTAL);
    uqr_main<<<NBLK, THREADS, SMEM_TOTAL>>>(X, b1, b2, bq, Wh, bh, out);
}